// round 3
// baseline (speedup 1.0000x reference)
#include <cuda_runtime.h>
#include <math.h>

#define N_NODES 20000
#define N_EDGES 160000
#define F_IN 128
#define D 128
#define H 4
#define HD 512            // H*D
#define N_LAYERS 3

// ---------------- scratch (device globals; no runtime allocation) ------------
__device__ float g_xl[(size_t)N_NODES * HD];
__device__ float g_xr[(size_t)N_NODES * HD];
__device__ int   g_cnt[N_NODES];
__device__ float g_easum[N_NODES * 2];
__device__ int   g_offs[N_NODES + 1];
__device__ int   g_cursor[N_NODES];
__device__ int   g_csr[N_EDGES];

// ---------------- init ----------------
__global__ void init_kernel() {
    int i = blockIdx.x * blockDim.x + threadIdx.x;
    if (i < N_NODES) {
        g_cnt[i] = 0;
        g_easum[2 * i] = 0.f;
        g_easum[2 * i + 1] = 0.f;
    }
}

// ---------------- histogram of dst + edge_attr sums ----------------
__global__ void count_kernel(const int* __restrict__ dst,
                             const float* __restrict__ eattr) {
    int e = blockIdx.x * blockDim.x + threadIdx.x;
    if (e < N_EDGES) {
        int d = dst[e];
        atomicAdd(&g_cnt[d], 1);
        atomicAdd(&g_easum[2 * d], eattr[2 * e]);
        atomicAdd(&g_easum[2 * d + 1], eattr[2 * e + 1]);
    }
}

// ---------------- single-block exclusive scan over 20000 counters ------------
__global__ void scan_kernel() {
    __shared__ int sm[1024];
    __shared__ int base_s;
    int tid = threadIdx.x;
    if (tid == 0) base_s = 0;
    __syncthreads();
    for (int start = 0; start < N_NODES; start += 1024) {
        int i = start + tid;
        int v = (i < N_NODES) ? g_cnt[i] : 0;
        sm[tid] = v;
        __syncthreads();
        #pragma unroll
        for (int off = 1; off < 1024; off <<= 1) {
            int t = (tid >= off) ? sm[tid - off] : 0;
            __syncthreads();
            sm[tid] += t;
            __syncthreads();
        }
        int incl = sm[tid];
        int base = base_s;
        if (i < N_NODES) {
            int excl = base + incl - v;
            g_offs[i] = excl;
            g_cursor[i] = excl;
        }
        __syncthreads();
        if (tid == 1023) base_s = base + sm[1023];
        __syncthreads();
    }
    if (tid == 0) g_offs[N_NODES] = N_EDGES;
}

// ---------------- scatter edge ids into CSR ----------------
__global__ void fill_kernel(const int* __restrict__ dst) {
    int e = blockIdx.x * blockDim.x + threadIdx.x;
    if (e < N_EDGES) {
        int d = dst[e];
        int pos = atomicAdd(&g_cursor[d], 1);
        g_csr[pos] = e;
    }
}

// ---------------- fp32 tiled GEMM with bias ----------------
// C[M,NCOLS] = A[M,128] @ B[128,NCOLS] + bias
// DSTSEL: 0 -> Cparam, 1 -> g_xl, 2 -> g_xr
template <int NCOLS, int DSTSEL>
__global__ void __launch_bounds__(256)
gemm_bias(const float* __restrict__ A, const float* __restrict__ B,
          const float* __restrict__ bias, float* __restrict__ Cparam, int M) {
    float* C;
    if (DSTSEL == 1)      C = g_xl;
    else if (DSTSEL == 2) C = g_xr;
    else                  C = Cparam;

    const int BM = 64, BN = 64, BK = 64, K = 128;
    __shared__ float As[BK][BM + 4];   // transposed: As[k][m]
    __shared__ float Bs[BK][BN];

    int n0 = blockIdx.x * BN;
    int m0 = blockIdx.y * BM;
    int t = threadIdx.x;
    int tx = t & 15;        // 0..15 -> 4 cols each
    int ty = t >> 4;        // 0..15 -> 4 rows each

    float acc[4][4] = {};

    for (int k0 = 0; k0 < K; k0 += BK) {
        #pragma unroll
        for (int i = 0; i < 4; i++) {
            int q = t + 256 * i;     // 0..1023
            int r = q >> 4;          // 0..63
            int c4 = q & 15;         // 0..15 (quad of 4 floats)
            int gm = m0 + r;
            float4 va = make_float4(0.f, 0.f, 0.f, 0.f);
            if (gm < M) va = *(const float4*)&A[(size_t)gm * K + k0 + 4 * c4];
            As[4 * c4 + 0][r] = va.x;
            As[4 * c4 + 1][r] = va.y;
            As[4 * c4 + 2][r] = va.z;
            As[4 * c4 + 3][r] = va.w;
            float4 vb = *(const float4*)&B[(size_t)(k0 + r) * NCOLS + n0 + 4 * c4];
            *(float4*)&Bs[r][4 * c4] = vb;
        }
        __syncthreads();
        #pragma unroll
        for (int k = 0; k < BK; k++) {
            float a[4], b[4];
            #pragma unroll
            for (int i = 0; i < 4; i++) a[i] = As[k][ty * 4 + i];
            #pragma unroll
            for (int j = 0; j < 4; j++) b[j] = Bs[k][tx * 4 + j];
            #pragma unroll
            for (int i = 0; i < 4; i++)
                #pragma unroll
                for (int j = 0; j < 4; j++)
                    acc[i][j] += a[i] * b[j];
        }
        __syncthreads();
    }

    #pragma unroll
    for (int i = 0; i < 4; i++) {
        int gm = m0 + ty * 4 + i;
        if (gm < M) {
            #pragma unroll
            for (int j = 0; j < 4; j++) {
                int gn = n0 + tx * 4 + j;
                C[(size_t)gm * NCOLS + gn] = acc[i][j] + bias[gn];
            }
        }
    }
}

// ---------------- fused GATv2 edge/aggregate kernel ----------------
// one block (128 thr) per node; warp h handles head h; lane l handles d=4l..4l+3
__global__ void __launch_bounds__(128)
edge_kernel(const int* __restrict__ esrc,
            const float* __restrict__ eattr,
            const float* __restrict__ We,       // [2,512]
            const float* __restrict__ att,      // [4,128]
            const float* __restrict__ bias_out, // [128]
            float* __restrict__ hout) {         // [N,128]
    int n = blockIdx.x;
    int h = threadIdx.x >> 5;
    int l = threadIdx.x & 31;

    __shared__ float We_sm[2 * HD];
    __shared__ float comb[H][D];
    for (int i = threadIdx.x; i < 2 * HD; i += 128) We_sm[i] = We[i];
    __syncthreads();

    int base = h * D + 4 * l;
    float4 xr4 = *(const float4*)&g_xr[(size_t)n * HD + base];
    float4 at4 = *(const float4*)&att[base];
    float4 we0 = *(const float4*)&We_sm[base];
    float4 we1 = *(const float4*)&We_sm[HD + base];

    float4 acc = make_float4(0.f, 0.f, 0.f, 0.f);
    float m = -INFINITY, denom = 0.f;

    int rs = g_offs[n], re = g_offs[n + 1];
    float inv = 1.0f / fmaxf((float)(re - rs), 1.0f);

    for (int idx = rs; idx <= re; ++idx) {
        int s;
        float ea0, ea1;
        if (idx < re) {
            int e = g_csr[idx];
            s = esrc[e];
            ea0 = eattr[2 * e];
            ea1 = eattr[2 * e + 1];
        } else {  // self-loop, fill_value='mean'
            s = n;
            ea0 = g_easum[2 * n] * inv;
            ea1 = g_easum[2 * n + 1] * inv;
        }
        float4 xl4 = *(const float4*)&g_xl[(size_t)s * HD + base];
        float t0 = xl4.x + xr4.x + ea0 * we0.x + ea1 * we1.x;
        float t1 = xl4.y + xr4.y + ea0 * we0.y + ea1 * we1.y;
        float t2 = xl4.z + xr4.z + ea0 * we0.z + ea1 * we1.z;
        float t3 = xl4.w + xr4.w + ea0 * we0.w + ea1 * we1.w;
        t0 = (t0 > 0.f) ? t0 : 0.2f * t0;
        t1 = (t1 > 0.f) ? t1 : 0.2f * t1;
        t2 = (t2 > 0.f) ? t2 : 0.2f * t2;
        t3 = (t3 > 0.f) ? t3 : 0.2f * t3;
        float p = t0 * at4.x + t1 * at4.y + t2 * at4.z + t3 * at4.w;
        #pragma unroll
        for (int off = 16; off > 0; off >>= 1)
            p += __shfl_xor_sync(0xffffffffu, p, off);
        float logit = p;

        // online softmax update
        float nm = fmaxf(m, logit);
        float r = __expf(m - nm);       // exp(-inf)=0 on first edge
        float w = __expf(logit - nm);
        acc.x = acc.x * r + w * xl4.x;
        acc.y = acc.y * r + w * xl4.y;
        acc.z = acc.z * r + w * xl4.z;
        acc.w = acc.w * r + w * xl4.w;
        denom = denom * r + w;
        m = nm;
    }

    float invd = 1.0f / denom;
    comb[h][4 * l + 0] = acc.x * invd;
    comb[h][4 * l + 1] = acc.y * invd;
    comb[h][4 * l + 2] = acc.z * invd;
    comb[h][4 * l + 3] = acc.w * invd;
    __syncthreads();

    int d = threadIdx.x;  // 0..127
    float v = 0.25f * (comb[0][d] + comb[1][d] + comb[2][d] + comb[3][d]) + bias_out[d];
    hout[(size_t)n * D + d] = (v > 0.f) ? v : 0.01f * v;
}

// ---------------- launch ----------------
extern "C" void kernel_launch(void* const* d_in, const int* in_sizes, int n_in,
                              void* d_out, int out_size) {
    const float* x            = (const float*)d_in[0];
    const int* eidx           = (const int*)d_in[1];   // int32 (JAX x64 disabled)
    const float* eattr        = (const float*)d_in[2];
    const float* Wf           = (const float*)d_in[3];
    const float* bf           = (const float*)d_in[4];
    const float* Wl           = (const float*)d_in[5];
    const float* bl           = (const float*)d_in[6];
    const float* Wr           = (const float*)d_in[7];
    const float* br           = (const float*)d_in[8];
    const float* We           = (const float*)d_in[9];
    const float* att          = (const float*)d_in[10];
    const float* bias_out     = (const float*)d_in[11];
    float* h                  = (float*)d_out;   // [N,128] doubles as hidden state

    const int* esrc = eidx;            // row 0
    const int* edst = eidx + N_EDGES;  // row 1

    // CSR build (dst-grouped), reused across all layers
    init_kernel<<<(N_NODES + 255) / 256, 256>>>();
    count_kernel<<<(N_EDGES + 255) / 256, 256>>>(edst, eattr);
    scan_kernel<<<1, 1024>>>();
    fill_kernel<<<(N_EDGES + 255) / 256, 256>>>(edst);

    // h0 = x @ Wf + bf
    {
        dim3 grid(D / 64, (N_NODES + 63) / 64);
        gemm_bias<D, 0><<<grid, 256>>>(x, Wf, bf, h, N_NODES);
    }

    for (int layer = 0; layer < N_LAYERS; ++layer) {
        dim3 grid(HD / 64, (N_NODES + 63) / 64);
        gemm_bias<HD, 1><<<grid, 256>>>(h, Wl, bl, nullptr, N_NODES);
        gemm_bias<HD, 2><<<grid, 256>>>(h, Wr, br, nullptr, N_NODES);
        edge_kernel<<<N_NODES, 128>>>(esrc, eattr, We, att, bias_out, h);
    }
}

// round 5
// speedup vs baseline: 1.4606x; 1.4606x over previous
#include <cuda_runtime.h>
#include <cuda_bf16.h>
#include <math.h>
#include <stdint.h>

#define N_NODES 20000
#define N_EDGES 160000
#define D 128
#define H 4
#define HD 512
#define N_LAYERS 3
#define KK 256            // split storage: 128 hi | 128 lo

// ---------------- scratch (device globals) ------------
__device__ float g_xl[(size_t)N_NODES * HD];
__device__ float g_xr[(size_t)N_NODES * HD];
__device__ __nv_bfloat16 g_hh[(size_t)N_NODES * KK];      // split activations [hi|lo]
__device__ __nv_bfloat16 g_wlr[(size_t)1024 * KK];        // split [Wl|Wr]^T [n][hi|lo]
__device__ __nv_bfloat16 g_wf[(size_t)128 * KK];          // split Wf^T
__device__ float g_blr[1024];
__device__ int   g_cnt[N_NODES];
__device__ float g_easum[N_NODES * 2];
__device__ int   g_offs[N_NODES + 1];
__device__ int   g_cursor[N_NODES];
__device__ int   g_csr[N_EDGES];

__device__ __forceinline__ uint32_t smem_u32(const void* p) {
    uint32_t a;
    asm("{ .reg .u64 t; cvta.to.shared.u64 t, %1; cvt.u32.u64 %0, t; }" : "=r"(a) : "l"(p));
    return a;
}

// ---------------- CSR build ----------------
__global__ void init_kernel() {
    int i = blockIdx.x * blockDim.x + threadIdx.x;
    if (i < N_NODES) { g_cnt[i] = 0; g_easum[2*i] = 0.f; g_easum[2*i+1] = 0.f; }
}
__global__ void count_kernel(const int* __restrict__ dst, const float* __restrict__ eattr) {
    int e = blockIdx.x * blockDim.x + threadIdx.x;
    if (e < N_EDGES) {
        int d = dst[e];
        atomicAdd(&g_cnt[d], 1);
        atomicAdd(&g_easum[2*d],   eattr[2*e]);
        atomicAdd(&g_easum[2*d+1], eattr[2*e+1]);
    }
}
__global__ void scan_kernel() {
    __shared__ int sm[1024];
    __shared__ int base_s;
    int tid = threadIdx.x;
    if (tid == 0) base_s = 0;
    __syncthreads();
    for (int start = 0; start < N_NODES; start += 1024) {
        int i = start + tid;
        int v = (i < N_NODES) ? g_cnt[i] : 0;
        sm[tid] = v;
        __syncthreads();
        #pragma unroll
        for (int off = 1; off < 1024; off <<= 1) {
            int t = (tid >= off) ? sm[tid - off] : 0;
            __syncthreads();
            sm[tid] += t;
            __syncthreads();
        }
        int incl = sm[tid], base = base_s;
        if (i < N_NODES) { g_offs[i] = base + incl - v; g_cursor[i] = base + incl - v; }
        __syncthreads();
        if (tid == 1023) base_s = base + sm[1023];
        __syncthreads();
    }
    if (tid == 0) g_offs[N_NODES] = N_EDGES;
}
__global__ void fill_kernel(const int* __restrict__ dst) {
    int e = blockIdx.x * blockDim.x + threadIdx.x;
    if (e < N_EDGES) g_csr[atomicAdd(&g_cursor[dst[e]], 1)] = e;
}

// ---------------- fp32 -> split bf16 ----------------
__device__ __forceinline__ void split_bf16(float v, __nv_bfloat16& hi, __nv_bfloat16& lo) {
    hi = __float2bfloat16(v);
    lo = __float2bfloat16(v - __bfloat162float(hi));
}
__global__ void split_act_kernel(const float* __restrict__ src) {
    int i = blockIdx.x * blockDim.x + threadIdx.x;
    if (i < N_NODES * 128) {
        int r = i >> 7, c = i & 127;
        __nv_bfloat16 hi, lo;
        split_bf16(src[i], hi, lo);
        g_hh[(size_t)r * KK + c] = hi;
        g_hh[(size_t)r * KK + 128 + c] = lo;
    }
}
__global__ void prep_wlr_kernel(const float* __restrict__ Wl, const float* __restrict__ Wr,
                                const float* __restrict__ bl, const float* __restrict__ br) {
    int i = blockIdx.x * blockDim.x + threadIdx.x;
    if (i < 1024 * 128) {
        int n = i >> 7, k = i & 127;
        float v = (n < 512) ? Wl[k * 512 + n] : Wr[k * 512 + (n - 512)];
        __nv_bfloat16 hi, lo;
        split_bf16(v, hi, lo);
        g_wlr[(size_t)n * KK + k] = hi;
        g_wlr[(size_t)n * KK + 128 + k] = lo;
        if (k == 0) g_blr[n] = (n < 512) ? bl[n] : br[n - 512];
    }
}
__global__ void prep_wf_kernel(const float* __restrict__ Wf) {
    int i = blockIdx.x * blockDim.x + threadIdx.x;
    if (i < 128 * 128) {
        int n = i >> 7, k = i & 127;
        __nv_bfloat16 hi, lo;
        split_bf16(Wf[k * 128 + n], hi, lo);
        g_wf[(size_t)n * KK + k] = hi;
        g_wf[(size_t)n * KK + 128 + k] = lo;
    }
}

// ---------------- bf16 mma.sync GEMM (split-K error compensation) ----------------
// CTA tile 128(m) x 128(n), smem-resident K=256 ([hi|lo]); 24 k16-steps cover
// AhiBhi + AloBhi + AhiBlo (AloBlo ~2^-16 dropped).
// 8 warps: wm = wid&3 (m 32 each), wn = wid>>2 (n 64 each).
// DSTSEL 0: C = Cparam [M,128] + bias_param. DSTSEL 3: cols<512 -> g_xl else g_xr, + g_blr.
#define LDK 264                 // row stride in bf16 (256 + 8 pad; conflict-free ldmatrix)
#define LDKB (LDK * 2)          // 528 bytes
#define TILE_BYTES (128 * LDKB) // 67584
#define GEMM_SMEM (2 * TILE_BYTES)

__device__ __forceinline__ void ldsm4(uint32_t* r, uint32_t addr) {
    asm volatile("ldmatrix.sync.aligned.m8n8.x4.shared.b16 {%0,%1,%2,%3}, [%4];"
                 : "=r"(r[0]), "=r"(r[1]), "=r"(r[2]), "=r"(r[3]) : "r"(addr));
}
__device__ __forceinline__ void mma16816(float* c, const uint32_t* a, const uint32_t* b) {
    asm volatile(
        "mma.sync.aligned.m16n8k16.row.col.f32.bf16.bf16.f32 "
        "{%0,%1,%2,%3}, {%4,%5,%6,%7}, {%8,%9}, {%0,%1,%2,%3};"
        : "+f"(c[0]), "+f"(c[1]), "+f"(c[2]), "+f"(c[3])
        : "r"(a[0]), "r"(a[1]), "r"(a[2]), "r"(a[3]), "r"(b[0]), "r"(b[1]));
}

template <int DSTSEL>
__global__ void __launch_bounds__(256)
mma_gemm(const float* __restrict__ bias_param, float* __restrict__ Cparam, int M) {
    extern __shared__ char smem[];
    uint32_t usb = smem_u32(smem);
    int tid = threadIdx.x, wid = tid >> 5, lane = tid & 31;
    int m0 = blockIdx.y * 128;
    int n0 = blockIdx.x * 128;

    const __nv_bfloat16* Bw = (DSTSEL == 0) ? g_wf : g_wlr;
    const float* bias = (DSTSEL == 0) ? bias_param : g_blr;

    // ---- load A tile: rows m0..m0+127 of g_hh (256 bf16 each) ----
    #pragma unroll
    for (int c = tid; c < 4096; c += 256) {
        int r = c >> 5;
        int kc = (c & 31) * 8;
        int gm = m0 + r;
        uint4 v = make_uint4(0, 0, 0, 0);
        if (gm < M) v = *(const uint4*)&g_hh[(size_t)gm * KK + kc];
        *(uint4*)(smem + r * LDKB + kc * 2) = v;
    }
    // ---- load B tile: rows n0..n0+127 of Bw ----
    #pragma unroll
    for (int c = tid; c < 4096; c += 256) {
        int r = c >> 5;
        int kc = (c & 31) * 8;
        uint4 v = *(const uint4*)&Bw[(size_t)(n0 + r) * KK + kc];
        *(uint4*)(smem + TILE_BYTES + r * LDKB + kc * 2) = v;
    }
    __syncthreads();

    int wm = wid & 3;       // m sub-tile (32 rows)
    int wn = wid >> 2;      // n sub-tile (64 cols)

    // ldmatrix lane address bases
    uint32_t aoff = usb + (uint32_t)((wm * 32 + (lane & 15)) * LDKB + ((lane >> 4) * 8) * 2);
    uint32_t boff = usb + TILE_BYTES +
        (uint32_t)((wn * 64 + ((lane >> 4) << 3) + (lane & 7)) * LDKB + (((lane >> 3) & 1) * 8) * 2);

    float acc[2][8][4];
    #pragma unroll
    for (int i = 0; i < 2; i++)
        #pragma unroll
        for (int j = 0; j < 8; j++)
            #pragma unroll
            for (int q = 0; q < 4; q++) acc[i][j][q] = 0.f;

    #pragma unroll
    for (int t = 0; t < 24; t++) {
        int k8 = t & 7, term = t >> 3;
        int ak = ((term == 1) ? 128 : 0) + k8 * 16;   // A col start (bf16 idx)
        int bk = ((term == 2) ? 128 : 0) + k8 * 16;   // B col start

        uint32_t ra[2][4];
        ldsm4(ra[0], aoff + ak * 2);
        ldsm4(ra[1], aoff + ak * 2 + 16 * LDKB);

        uint32_t rb[4][4];
        #pragma unroll
        for (int g = 0; g < 4; g++)
            ldsm4(rb[g], boff + bk * 2 + g * 16 * LDKB);

        #pragma unroll
        for (int mi = 0; mi < 2; mi++)
            #pragma unroll
            for (int g = 0; g < 4; g++) {
                mma16816(acc[mi][2 * g],     ra[mi], &rb[g][0]);
                mma16816(acc[mi][2 * g + 1], ra[mi], &rb[g][2]);
            }
    }

    // ---- epilogue ----
    int lr = lane >> 2;          // 0..7
    int lc = (lane & 3) * 2;     // 0,2,4,6
    #pragma unroll
    for (int mi = 0; mi < 2; mi++) {
        #pragma unroll
        for (int ni = 0; ni < 8; ni++) {
            int gn = n0 + wn * 64 + ni * 8 + lc;
            float bx = bias[gn], by = bias[gn + 1];
            #pragma unroll
            for (int half = 0; half < 2; half++) {
                int gm = m0 + wm * 32 + mi * 16 + lr + half * 8;
                if (gm < M) {
                    float2 v = make_float2(acc[mi][ni][2 * half] + bx,
                                           acc[mi][ni][2 * half + 1] + by);
                    if (DSTSEL == 0) {
                        *(float2*)&Cparam[(size_t)gm * 128 + gn] = v;
                    } else {
                        if (gn < 512) *(float2*)&g_xl[(size_t)gm * 512 + gn] = v;
                        else          *(float2*)&g_xr[(size_t)gm * 512 + (gn - 512)] = v;
                    }
                }
            }
        }
    }
}

// ---------------- fused GATv2 edge/aggregate kernel ----------------
__global__ void __launch_bounds__(128)
edge_kernel(const int* __restrict__ esrc,
            const float* __restrict__ eattr,
            const float* __restrict__ We,
            const float* __restrict__ att,
            const float* __restrict__ bias_out,
            float* __restrict__ hout) {
    int n = blockIdx.x;
    int h = threadIdx.x >> 5;
    int l = threadIdx.x & 31;

    __shared__ float We_sm[2 * HD];
    __shared__ float comb[H][D];
    for (int i = threadIdx.x; i < 2 * HD; i += 128) We_sm[i] = We[i];
    __syncthreads();

    int base = h * D + 4 * l;
    float4 xr4 = *(const float4*)&g_xr[(size_t)n * HD + base];
    float4 at4 = *(const float4*)&att[base];
    float4 we0 = *(const float4*)&We_sm[base];
    float4 we1 = *(const float4*)&We_sm[HD + base];

    float4 acc = make_float4(0.f, 0.f, 0.f, 0.f);
    float m = -INFINITY, denom = 0.f;

    int rs = g_offs[n], re = g_offs[n + 1];
    float inv = 1.0f / fmaxf((float)(re - rs), 1.0f);

    for (int idx = rs; idx <= re; ++idx) {
        int s;
        float ea0, ea1;
        if (idx < re) {
            int e = g_csr[idx];
            s = esrc[e];
            ea0 = eattr[2 * e];
            ea1 = eattr[2 * e + 1];
        } else {
            s = n;
            ea0 = g_easum[2 * n] * inv;
            ea1 = g_easum[2 * n + 1] * inv;
        }
        float4 xl4 = *(const float4*)&g_xl[(size_t)s * HD + base];
        float t0 = xl4.x + xr4.x + ea0 * we0.x + ea1 * we1.x;
        float t1 = xl4.y + xr4.y + ea0 * we0.y + ea1 * we1.y;
        float t2 = xl4.z + xr4.z + ea0 * we0.z + ea1 * we1.z;
        float t3 = xl4.w + xr4.w + ea0 * we0.w + ea1 * we1.w;
        t0 = (t0 > 0.f) ? t0 : 0.2f * t0;
        t1 = (t1 > 0.f) ? t1 : 0.2f * t1;
        t2 = (t2 > 0.f) ? t2 : 0.2f * t2;
        t3 = (t3 > 0.f) ? t3 : 0.2f * t3;
        float p = t0 * at4.x + t1 * at4.y + t2 * at4.z + t3 * at4.w;
        #pragma unroll
        for (int off = 16; off > 0; off >>= 1)
            p += __shfl_xor_sync(0xffffffffu, p, off);
        float logit = p;

        float nm = fmaxf(m, logit);
        float r = __expf(m - nm);
        float w = __expf(logit - nm);
        acc.x = acc.x * r + w * xl4.x;
        acc.y = acc.y * r + w * xl4.y;
        acc.z = acc.z * r + w * xl4.z;
        acc.w = acc.w * r + w * xl4.w;
        denom = denom * r + w;
        m = nm;
    }

    float invd = 1.0f / denom;
    comb[h][4 * l + 0] = acc.x * invd;
    comb[h][4 * l + 1] = acc.y * invd;
    comb[h][4 * l + 2] = acc.z * invd;
    comb[h][4 * l + 3] = acc.w * invd;
    __syncthreads();

    int d = threadIdx.x;
    float v = 0.25f * (comb[0][d] + comb[1][d] + comb[2][d] + comb[3][d]) + bias_out[d];
    hout[(size_t)n * D + d] = (v > 0.f) ? v : 0.01f * v;
}

// ---------------- launch ----------------
extern "C" void kernel_launch(void* const* d_in, const int* in_sizes, int n_in,
                              void* d_out, int out_size) {
    const float* x        = (const float*)d_in[0];
    const int* eidx       = (const int*)d_in[1];
    const float* eattr    = (const float*)d_in[2];
    const float* Wf       = (const float*)d_in[3];
    const float* bf       = (const float*)d_in[4];
    const float* Wl       = (const float*)d_in[5];
    const float* bl       = (const float*)d_in[6];
    const float* Wr       = (const float*)d_in[7];
    const float* br       = (const float*)d_in[8];
    const float* We       = (const float*)d_in[9];
    const float* att      = (const float*)d_in[10];
    const float* bias_out = (const float*)d_in[11];
    float* h              = (float*)d_out;

    const int* esrc = eidx;
    const int* edst = eidx + N_EDGES;

    cudaFuncSetAttribute(mma_gemm<0>, cudaFuncAttributeMaxDynamicSharedMemorySize, GEMM_SMEM);
    cudaFuncSetAttribute(mma_gemm<3>, cudaFuncAttributeMaxDynamicSharedMemorySize, GEMM_SMEM);

    // CSR build
    init_kernel<<<(N_NODES + 255) / 256, 256>>>();
    count_kernel<<<(N_EDGES + 255) / 256, 256>>>(edst, eattr);
    scan_kernel<<<1, 1024>>>();
    fill_kernel<<<(N_EDGES + 255) / 256, 256>>>(edst);

    // weight prep (split bf16, transposed)
    prep_wlr_kernel<<<(1024 * 128 + 255) / 256, 256>>>(Wl, Wr, bl, br);
    prep_wf_kernel<<<(128 * 128 + 255) / 256, 256>>>(Wf);

    const int MTILES = (N_NODES + 127) / 128;   // 157

    // h0 = x @ Wf + bf
    split_act_kernel<<<(N_NODES * 128 + 255) / 256, 256>>>(x);
    {
        dim3 grid(1, MTILES);
        mma_gemm<0><<<grid, 256, GEMM_SMEM>>>(bf, h, N_NODES);
    }

    for (int layer = 0; layer < N_LAYERS; ++layer) {
        split_act_kernel<<<(N_NODES * 128 + 255) / 256, 256>>>(h);
        dim3 grid(8, MTILES);
        mma_gemm<3><<<grid, 256, GEMM_SMEM>>>(nullptr, nullptr, N_NODES);
        edge_kernel<<<N_NODES, 128>>>(esrc, eattr, We, att, bias_out, h);
    }
}